// round 3
// baseline (speedup 1.0000x reference)
#include <cuda_runtime.h>
#include <math.h>
#include <stdint.h>

#define NC 10

// ---------------- scratch (static device arrays; no runtime allocation) ----------------
__device__ float g_h[52428800];      // [512][256][20][20] conv1 output
__device__ float g_u[4718592];       // [512][1152][8] primary capsules (pre/post squash in place)
__device__ float g_caps[81920];      // [512][10][16]
__device__ float g_d0[81920];        // [512][160]
__device__ float g_d1[262144];       // [512][512]
__device__ float g_d2[524288];       // [512][1024]

// ---------------- packed fp32x2 FMA (SASS FFMA2; only reachable via PTX) ----------------
__device__ __forceinline__ void ffma2(float2& c, const float2 a, const float2 b) {
    asm("fma.rn.f32x2 %0, %1, %2, %0;"
        : "+l"(reinterpret_cast<unsigned long long&>(c))
        : "l"(reinterpret_cast<const unsigned long long&>(a)),
          "l"(reinterpret_cast<const unsigned long long&>(b)));
}

__device__ __forceinline__ void cp_async4(uint32_t saddr, const float* gptr) {
    asm volatile("cp.async.ca.shared.global [%0], [%1], 4;" :: "r"(saddr), "l"(gptr));
}
__device__ __forceinline__ void cp_commit() { asm volatile("cp.async.commit_group;"); }
__device__ __forceinline__ void cp_wait0()  { asm volatile("cp.async.wait_group 0;" ::: "memory"); }

// ---------------- conv1: x[512,1,28,28] * w[256,1,9,9] -> relu(h)[512,256,20,20] ----------------
__global__ __launch_bounds__(640) void conv1_kernel(const float* __restrict__ x,
                                                    const float* __restrict__ w,
                                                    const float* __restrict__ bias) {
    __shared__ __align__(16) float img[784];
    __shared__ float ws[2592];   // 32 oc * 81 taps
    __shared__ float bs[32];
    int b = blockIdx.y, ocg = blockIdx.x, t = threadIdx.x;
    const float4* xim = (const float4*)(x + (size_t)b * 784);
    for (int i = t; i < 196; i += 640) ((float4*)img)[i] = xim[i];
    for (int i = t; i < 2592; i += 640) ws[i] = w[(size_t)ocg * 2592 + i];
    if (t < 32) bs[t] = bias[ocg * 32 + t];
    __syncthreads();
    int oc = t & 31, y = t >> 5;            // 32 oc x 20 output rows
    float acc[20];
#pragma unroll
    for (int i = 0; i < 20; i++) acc[i] = 0.f;
    for (int dy = 0; dy < 9; dy++) {
        float row[28];
        const float4* rp = (const float4*)&img[(y + dy) * 28];
#pragma unroll
        for (int i = 0; i < 7; i++) {
            float4 v = rp[i];
            row[4*i] = v.x; row[4*i+1] = v.y; row[4*i+2] = v.z; row[4*i+3] = v.w;
        }
#pragma unroll
        for (int dx = 0; dx < 9; dx++) {
            float wv = ws[oc * 81 + dy * 9 + dx];
#pragma unroll
            for (int xo = 0; xo < 20; xo++) acc[xo] = fmaf(wv, row[xo + dx], acc[xo]);
        }
    }
    float bv = bs[oc];
    float4* hp = (float4*)(g_h + (((size_t)b * 256 + ocg * 32 + oc) * 20 + y) * 20);
#pragma unroll
    for (int i = 0; i < 5; i++) {
        float4 v;
        v.x = fmaxf(acc[4*i]   + bv, 0.f);
        v.y = fmaxf(acc[4*i+1] + bv, 0.f);
        v.z = fmaxf(acc[4*i+2] + bv, 0.f);
        v.w = fmaxf(acc[4*i+3] + bv, 0.f);
        hp[i] = v;
    }
}

// ------- conv2 (primary caps): h[512,256,20,20] * w[256,256,9,9] stride2 -> u_raw[b][r][d] -------
// Block: 4 images (2 pairs) x 64 oc, 128 threads. Thread = (pair, oc), accumulates the 6x6
// tile for BOTH images of its pair in float2 accumulators driven by FFMA2 (fma.rn.f32x2).
// Images staged pair-interleaved in smem (float2) so both lanes load with one LDS; within a
// warp all lanes share the image address (broadcast, conflict-free). Weight rows stride 81
// (odd) -> conflict-free. Double-buffered: weights via cp.async, images via reg pipeline.
__global__ __launch_bounds__(128, 3) void conv2_kernel(const float* __restrict__ w,
                                                       const float* __restrict__ bias) {
    extern __shared__ __align__(16) char sm_raw[];
    float2* ibuf = (float2*)sm_raw;                 // [2][2 pairs][400]
    float*  wbuf = (float*)(sm_raw + 12800);        // [2][64*81]
    uint32_t wsm = (uint32_t)__cvta_generic_to_shared(wbuf);

    int ocg = blockIdx.x, bq = blockIdx.y, t = threadIdx.x;
    int pair = t >> 6, ocl = t & 63;
    int ocbase = ocg * 64;

    // ---- prologue: stage ci=0 into buffer 0 ----
    {
        float2 ir[7];
#pragma unroll
        for (int k = 0; k < 7; k++) {
            int j = t + k * 128;
            if (j < 800) {
                int p = (j >= 400), pos = j - p * 400;
                const float* h0 = g_h + ((size_t)(bq * 4 + 2 * p) * 256) * 400 + pos;
                ir[k] = make_float2(h0[0], h0[102400]);
            }
        }
#pragma unroll
        for (int k = 0; k < 7; k++) {
            int j = t + k * 128;
            if (j < 800) ibuf[j] = ir[k];
        }
        for (int j = t; j < 5184; j += 128) {
            int o = j / 81, tap = j - o * 81;
            cp_async4(wsm + (uint32_t)j * 4, w + (size_t)(ocbase + o) * 20736 + tap);
        }
        cp_commit();
    }

    float2 acc[36];
#pragma unroll
    for (int i = 0; i < 36; i++) acc[i] = make_float2(0.f, 0.f);

    for (int ci = 0; ci < 256; ci++) {
        cp_wait0();
        __syncthreads();
        int cb = ci & 1, nb = cb ^ 1;

        // prefetch ci+1
        float2 ir[7];
        if (ci < 255) {
            int ci1 = ci + 1;
#pragma unroll
            for (int k = 0; k < 7; k++) {
                int j = t + k * 128;
                if (j < 800) {
                    int p = (j >= 400), pos = j - p * 400;
                    const float* h0 = g_h + ((size_t)(bq * 4 + 2 * p) * 256 + ci1) * 400 + pos;
                    ir[k] = make_float2(h0[0], h0[102400]);
                }
            }
            for (int j = t; j < 5184; j += 128) {
                int o = j / 81, tap = j - o * 81;
                cp_async4(wsm + (uint32_t)(nb * 5184 + j) * 4,
                          w + (size_t)(ocbase + o) * 20736 + ci1 * 81 + tap);
            }
            cp_commit();
        }

        // ---- compute from current buffer ----
        const float2* im = ibuf + cb * 800 + pair * 400;
        const float* wrow = wbuf + cb * 5184 + ocl * 81;
#pragma unroll 1
        for (int dy = 0; dy < 9; dy++) {
            float2 w2[9];
#pragma unroll
            for (int dx = 0; dx < 9; dx++) {
                float wv = wrow[dy * 9 + dx];
                w2[dx] = make_float2(wv, wv);
            }
#pragma unroll
            for (int oy = 0; oy < 6; oy++) {
                const float2* rowp = im + (2 * oy + dy) * 20;
                float2 r[14];
                // first half: cols 0..13 -> ox 0..2
                {
                    const float4* rp = (const float4*)rowp;
#pragma unroll
                    for (int i = 0; i < 7; i++) {
                        float4 v = rp[i];
                        r[2*i]   = make_float2(v.x, v.y);
                        r[2*i+1] = make_float2(v.z, v.w);
                    }
                }
#pragma unroll
                for (int dx = 0; dx < 9; dx++)
#pragma unroll
                    for (int ox = 0; ox < 3; ox++)
                        ffma2(acc[oy * 6 + ox], w2[dx], r[2 * ox + dx]);
                // second half: cols 6..19 -> ox 3..5
                {
                    const float4* rp = (const float4*)(rowp + 6);
#pragma unroll
                    for (int i = 0; i < 7; i++) {
                        float4 v = rp[i];
                        r[2*i]   = make_float2(v.x, v.y);
                        r[2*i+1] = make_float2(v.z, v.w);
                    }
                }
#pragma unroll
                for (int dx = 0; dx < 9; dx++)
#pragma unroll
                    for (int ox = 3; ox < 6; ox++)
                        ffma2(acc[oy * 6 + ox], w2[dx], r[2 * ox + dx - 6]);
            }
        }

        // stash prefetched images into next buffer
        if (ci < 255) {
#pragma unroll
            for (int k = 0; k < 7; k++) {
                int j = t + k * 128;
                if (j < 800) ibuf[nb * 800 + j] = ir[k];
            }
        }
    }

    // ---- epilogue ----
    int oc = ocbase + ocl;
    int d = oc >> 5, m = oc & 31;
    float bv = bias[oc];
    int b0 = bq * 4 + 2 * pair;
    float* u0 = g_u + ((size_t)b0 * 1152 + m * 36) * 8 + d;
    float* u1 = u0 + 1152 * 8;
#pragma unroll
    for (int p = 0; p < 36; p++) {
        u0[p * 8] = acc[p].x + bv;
        u1[p * 8] = acc[p].y + bv;
    }
}

// ---------------- squash over capsule dim (8) in place ----------------
__global__ void squash_kernel() {
    int idx = blockIdx.x * 256 + threadIdx.x;
    if (idx >= 512 * 1152) return;
    float4* p = (float4*)(g_u + (size_t)idx * 8);
    float4 a = p[0], b = p[1];
    float sq = a.x*a.x + a.y*a.y + a.z*a.z + a.w*a.w
             + b.x*b.x + b.y*b.y + b.z*b.z + b.w*b.w;
    float sc = sq / ((1.f + sq) * sqrtf(sq));
    a.x *= sc; a.y *= sc; a.z *= sc; a.w *= sc;
    b.x *= sc; b.y *= sc; b.z *= sc; b.w *= sc;
    p[0] = a; p[1] = b;
}

// ---------------- fused priors + dynamic routing: one block per (class, image) ----------------
__global__ __launch_bounds__(256) void routing_kernel(const float* __restrict__ rw) {
    extern __shared__ float smf[];
    float* pr  = smf;                 // 1152*17
    float* lg  = smf + 1152 * 17;     // 1152
    float* red = lg + 1152;           // 8*17
    int c = blockIdx.x, b = blockIdx.y, t = threadIdx.x;
    int lane = t & 31, wid = t >> 5;
    const float* ub  = g_u + (size_t)b * 9216;
    const float* rwc = rw + (size_t)c * 147456;
    for (int r = t; r < 1152; r += 256) {
        const float4* uq = (const float4*)(ub + r * 8);
        float4 u0 = uq[0], u1 = uq[1];
        float uu[8] = {u0.x, u0.y, u0.z, u0.w, u1.x, u1.y, u1.z, u1.w};
        const float4* wp = (const float4*)(rwc + (size_t)r * 128);
        float acc[16];
#pragma unroll
        for (int o = 0; o < 16; o++) acc[o] = 0.f;
#pragma unroll
        for (int i = 0; i < 8; i++) {
            float ui = uu[i];
#pragma unroll
            for (int q = 0; q < 4; q++) {
                float4 wv = wp[i * 4 + q];
                acc[q*4+0] = fmaf(ui, wv.x, acc[q*4+0]);
                acc[q*4+1] = fmaf(ui, wv.y, acc[q*4+1]);
                acc[q*4+2] = fmaf(ui, wv.z, acc[q*4+2]);
                acc[q*4+3] = fmaf(ui, wv.w, acc[q*4+3]);
            }
        }
        float* pp = pr + r * 17;
#pragma unroll
        for (int o = 0; o < 16; o++) pp[o] = acc[o];
        lg[r] = 0.f;
    }
    __syncthreads();
    float v[16];
    for (int it = 0; it < 3; it++) {
        float mx = -3.0e38f;
        for (int r = t; r < 1152; r += 256) mx = fmaxf(mx, lg[r]);
#pragma unroll
        for (int off = 16; off; off >>= 1) mx = fmaxf(mx, __shfl_xor_sync(0xffffffffu, mx, off));
        if (lane == 0) red[wid] = mx;
        __syncthreads();
        float M = fmaxf(fmaxf(fmaxf(red[0], red[1]), fmaxf(red[2], red[3])),
                        fmaxf(fmaxf(red[4], red[5]), fmaxf(red[6], red[7])));
        __syncthreads();
        float s[16];
#pragma unroll
        for (int o = 0; o < 16; o++) s[o] = 0.f;
        float z = 0.f;
        for (int r = t; r < 1152; r += 256) {
            float e = expf(lg[r] - M);
            z += e;
            const float* pp = pr + r * 17;
#pragma unroll
            for (int o = 0; o < 16; o++) s[o] = fmaf(e, pp[o], s[o]);
        }
#pragma unroll
        for (int off = 16; off; off >>= 1) {
            z += __shfl_xor_sync(0xffffffffu, z, off);
#pragma unroll
            for (int o = 0; o < 16; o++) s[o] += __shfl_xor_sync(0xffffffffu, s[o], off);
        }
        if (lane == 0) {
            float* rr = red + wid * 17;
#pragma unroll
            for (int o = 0; o < 16; o++) rr[o] = s[o];
            rr[16] = z;
        }
        __syncthreads();
        float Z = 0.f, S[16];
#pragma unroll
        for (int o = 0; o < 16; o++) S[o] = 0.f;
#pragma unroll
        for (int ww = 0; ww < 8; ww++) {
            const float* rr = red + ww * 17;
            Z += rr[16];
#pragma unroll
            for (int o = 0; o < 16; o++) S[o] += rr[o];
        }
        float sq = 0.f;
#pragma unroll
        for (int o = 0; o < 16; o++) { v[o] = S[o] / Z; sq = fmaf(v[o], v[o], sq); }
        float sc = sq / ((1.f + sq) * sqrtf(sq));
#pragma unroll
        for (int o = 0; o < 16; o++) v[o] *= sc;
        if (it < 2) {
            __syncthreads();
            for (int r = t; r < 1152; r += 256) {
                const float* pp = pr + r * 17;
                float dot = 0.f;
#pragma unroll
                for (int o = 0; o < 16; o++) dot = fmaf(pp[o], v[o], dot);
                lg[r] += dot;
            }
            __syncthreads();
        }
    }
    if (t == 0) {
        float* cp = g_caps + ((size_t)b * NC + c) * 16;
#pragma unroll
        for (int o = 0; o < 16; o++) cp[o] = v[o];
    }
}

// ---------------- classes softmax + argmax mask -> decoder input ----------------
__global__ void classes_kernel(float* __restrict__ out_classes) {
    int b = blockIdx.x, lane = threadIdx.x;  // 32 threads
    float n2 = 0.f;
    if (lane < NC) {
        const float* cp = g_caps + ((size_t)b * NC + lane) * 16;
#pragma unroll
        for (int o = 0; o < 16; o++) n2 = fmaf(cp[o], cp[o], n2);
    }
    float nrm = (lane < NC) ? sqrtf(n2) : -3.0e38f;
    float mx = nrm;
#pragma unroll
    for (int off = 16; off; off >>= 1) mx = fmaxf(mx, __shfl_xor_sync(0xffffffffu, mx, off));
    float e = (lane < NC) ? expf(nrm - mx) : 0.f;
    float zz = e;
#pragma unroll
    for (int off = 16; off; off >>= 1) zz += __shfl_xor_sync(0xffffffffu, zz, off);
    if (lane < NC) out_classes[b * NC + lane] = e / zz;
    unsigned msk = __ballot_sync(0xffffffffu, nrm == mx);
    int am = __ffs(msk) - 1;   // first (lowest-index) max, matches jnp.argmax
    const float* ap = g_caps + ((size_t)b * NC + am) * 16;
    for (int j = lane; j < 160; j += 32)
        g_d0[b * 160 + j] = ((j >> 4) == am) ? ap[j & 15] : 0.f;
}

// ---------------- decoder GEMM: C[512,N] = act(A[512,K] @ W[N,K]^T + bias) ----------------
__global__ __launch_bounds__(256) void gemm_kernel(const float* __restrict__ A,
                                                   const float* __restrict__ W,
                                                   const float* __restrict__ bias,
                                                   float* __restrict__ C,
                                                   int N, int K, int act) {
    __shared__ float As[64][33];
    __shared__ float Bs[64][33];
    int tx = threadIdx.x & 15, ty = threadIdx.x >> 4;
    int m0 = blockIdx.y * 64, n0 = blockIdx.x * 64;
    float acc[4][4];
#pragma unroll
    for (int i = 0; i < 4; i++)
#pragma unroll
        for (int j = 0; j < 4; j++) acc[i][j] = 0.f;
    for (int k0 = 0; k0 < K; k0 += 32) {
        __syncthreads();
        for (int idx = threadIdx.x; idx < 2048; idx += 256) {
            int mm = idx >> 5, kk = idx & 31;
            As[mm][kk] = A[(size_t)(m0 + mm) * K + k0 + kk];
            Bs[mm][kk] = (n0 + mm < N) ? W[(size_t)(n0 + mm) * K + k0 + kk] : 0.f;
        }
        __syncthreads();
#pragma unroll
        for (int kk = 0; kk < 32; kk++) {
            float a[4], bb[4];
#pragma unroll
            for (int i = 0; i < 4; i++) a[i] = As[ty * 4 + i][kk];
#pragma unroll
            for (int j = 0; j < 4; j++) bb[j] = Bs[tx * 4 + j][kk];
#pragma unroll
            for (int i = 0; i < 4; i++)
#pragma unroll
                for (int j = 0; j < 4; j++) acc[i][j] = fmaf(a[i], bb[j], acc[i][j]);
        }
    }
#pragma unroll
    for (int i = 0; i < 4; i++) {
        int cm = m0 + ty * 4 + i;
#pragma unroll
        for (int j = 0; j < 4; j++) {
            int cn = n0 + tx * 4 + j;
            if (cn < N) {
                float val = acc[i][j] + bias[cn];
                val = act ? (1.f / (1.f + expf(-val))) : fmaxf(val, 0.f);
                C[(size_t)cm * N + cn] = val;
            }
        }
    }
}

extern "C" void kernel_launch(void* const* d_in, const int* in_sizes, int n_in,
                              void* d_out, int out_size) {
    const float* x   = (const float*)d_in[0];
    const float* c1w = (const float*)d_in[1];
    const float* c1b = (const float*)d_in[2];
    const float* pw  = (const float*)d_in[3];
    const float* pb  = (const float*)d_in[4];
    const float* rw  = (const float*)d_in[5];
    const float* w1  = (const float*)d_in[6];
    const float* b1  = (const float*)d_in[7];
    const float* w2  = (const float*)d_in[8];
    const float* b2  = (const float*)d_in[9];
    const float* w3  = (const float*)d_in[10];
    const float* b3  = (const float*)d_in[11];
    float* out = (float*)d_out;
    float* out_classes = out;              // [512,10]
    float* out_recon   = out + 512 * NC;   // [512,784]

    void *p_d0, *p_d1, *p_d2;
    cudaGetSymbolAddress(&p_d0, g_d0);
    cudaGetSymbolAddress(&p_d1, g_d1);
    cudaGetSymbolAddress(&p_d2, g_d2);

    conv1_kernel<<<dim3(8, 512), 640>>>(x, c1w, c1b);

    int c2sm = 12800 + 2 * 5184 * 4;  // 54272 B
    cudaFuncSetAttribute(conv2_kernel, cudaFuncAttributeMaxDynamicSharedMemorySize, c2sm);
    conv2_kernel<<<dim3(4, 128), 128, c2sm>>>(pw, pb);

    squash_kernel<<<(512 * 1152 + 255) / 256, 256>>>();

    size_t rsm = (size_t)(1152 * 17 + 1152 + 136) * sizeof(float);  // 83488 B
    cudaFuncSetAttribute(routing_kernel, cudaFuncAttributeMaxDynamicSharedMemorySize, (int)rsm);
    routing_kernel<<<dim3(10, 512), 256, rsm>>>(rw);

    classes_kernel<<<512, 32>>>(out_classes);

    gemm_kernel<<<dim3(8, 8),  256>>>((const float*)p_d0, w1, b1, (float*)p_d1, 512, 160, 0);
    gemm_kernel<<<dim3(16, 8), 256>>>((const float*)p_d1, w2, b2, (float*)p_d2, 1024, 512, 0);
    gemm_kernel<<<dim3(13, 8), 256>>>((const float*)p_d2, w3, b3, out_recon, 784, 1024, 1);
}

// round 5
// speedup vs baseline: 1.9173x; 1.9173x over previous
#include <cuda_runtime.h>
#include <cuda_bf16.h>
#include <math.h>
#include <stdint.h>

#define NC 10

// ---------------- scratch (static device arrays; no runtime allocation) ----------------
__device__ __nv_bfloat16 g_hh[52428800];  // [512 b][20 y][20 x][256 c] conv1 out, bf16 hi
__device__ __nv_bfloat16 g_hl[52428800];  // same, bf16 lo (residual)
__device__ __nv_bfloat16 g_wh[5308416];   // [81 dydx][256 ci][256 oc] weights hi
__device__ __nv_bfloat16 g_wl[5308416];   // weights lo
__device__ float g_u[4718592];            // [512][1152][8] primary capsules
__device__ float g_caps[81920];           // [512][10][16]
__device__ float g_d0[81920];             // [512][160]
__device__ float g_d1[262144];            // [512][512]
__device__ float g_d2[524288];            // [512][1024]

// ---------------- PTX helpers (all baseline sm_80+; no arch-'a' features) ----------------
__device__ __forceinline__ void cp16(uint32_t d, const void* s) {
    asm volatile("cp.async.cg.shared.global [%0], [%1], 16;" :: "r"(d), "l"(s));
}
__device__ __forceinline__ void cp_commit() { asm volatile("cp.async.commit_group;"); }
__device__ __forceinline__ void cp_wait0()  { asm volatile("cp.async.wait_group 0;" ::: "memory"); }
__device__ __forceinline__ void cp_wait1()  { asm volatile("cp.async.wait_group 1;" ::: "memory"); }

__device__ __forceinline__ void ldsm4(uint32_t* r, uint32_t addr) {
    asm volatile("ldmatrix.sync.aligned.m8n8.x4.shared.b16 {%0,%1,%2,%3}, [%4];"
        : "=r"(r[0]), "=r"(r[1]), "=r"(r[2]), "=r"(r[3]) : "r"(addr));
}
__device__ __forceinline__ void ldsm4t(uint32_t* r, uint32_t addr) {
    asm volatile("ldmatrix.sync.aligned.m8n8.x4.trans.shared.b16 {%0,%1,%2,%3}, [%4];"
        : "=r"(r[0]), "=r"(r[1]), "=r"(r[2]), "=r"(r[3]) : "r"(addr));
}
__device__ __forceinline__ void mma16816(float* c, const uint32_t* a, const uint32_t* b) {
    asm volatile("mma.sync.aligned.m16n8k16.row.col.f32.bf16.bf16.f32 "
        "{%0,%1,%2,%3}, {%4,%5,%6,%7}, {%8,%9}, {%0,%1,%2,%3};"
        : "+f"(c[0]), "+f"(c[1]), "+f"(c[2]), "+f"(c[3])
        : "r"(a[0]), "r"(a[1]), "r"(a[2]), "r"(a[3]), "r"(b[0]), "r"(b[1]));
}

// ---------------- weight prep: prim_w [256 oc][256 ci][81] -> [dydx][ci][oc] hi/lo bf16 ----------
__global__ void prep_w_kernel(const float* __restrict__ pw) {
    int idx = blockIdx.x * 256 + threadIdx.x;   // 65536 = ci*256 + oc
    int ci = idx >> 8, oc = idx & 255;
    const float* src = pw + (size_t)(oc * 256 + ci) * 81;
#pragma unroll 3
    for (int k = 0; k < 81; k++) {
        float w = src[k];
        __nv_bfloat16 hi = __float2bfloat16(w);
        __nv_bfloat16 lo = __float2bfloat16(w - __bfloat162float(hi));
        size_t o = ((size_t)k * 256 + ci) * 256 + oc;
        g_wh[o] = hi;
        g_wl[o] = lo;
    }
}

// ---------------- conv1: x[512,1,28,28] * w[256,1,9,9] -> relu -> NHWC bf16 hi/lo ----------------
__global__ __launch_bounds__(640) void conv1_kernel(const float* __restrict__ x,
                                                    const float* __restrict__ w,
                                                    const float* __restrict__ bias) {
    __shared__ __align__(16) float img[784];
    __shared__ float ws[2592];
    __shared__ float bs[32];
    int b = blockIdx.y, ocg = blockIdx.x, t = threadIdx.x;
    const float4* xim = (const float4*)(x + (size_t)b * 784);
    for (int i = t; i < 196; i += 640) ((float4*)img)[i] = xim[i];
    for (int i = t; i < 2592; i += 640) ws[i] = w[(size_t)ocg * 2592 + i];
    if (t < 32) bs[t] = bias[ocg * 32 + t];
    __syncthreads();
    int oc = t & 31, y = t >> 5;
    float acc[20];
#pragma unroll
    for (int i = 0; i < 20; i++) acc[i] = 0.f;
    for (int dy = 0; dy < 9; dy++) {
        float row[28];
        const float4* rp = (const float4*)&img[(y + dy) * 28];
#pragma unroll
        for (int i = 0; i < 7; i++) {
            float4 v = rp[i];
            row[4*i] = v.x; row[4*i+1] = v.y; row[4*i+2] = v.z; row[4*i+3] = v.w;
        }
#pragma unroll
        for (int dx = 0; dx < 9; dx++) {
            float wv = ws[oc * 81 + dy * 9 + dx];
#pragma unroll
            for (int xo = 0; xo < 20; xo++) acc[xo] = fmaf(wv, row[xo + dx], acc[xo]);
        }
    }
    float bv = bs[oc];
    size_t base = (((size_t)b * 20 + y) * 20) * 256 + ocg * 32 + oc;
#pragma unroll
    for (int i = 0; i < 20; i++) {
        float val = fmaxf(acc[i] + bv, 0.f);
        __nv_bfloat16 hi = __float2bfloat16(val);
        __nv_bfloat16 lo = __float2bfloat16(val - __bfloat162float(hi));
        g_hh[base + (size_t)i * 256] = hi;
        g_hl[base + (size_t)i * 256] = lo;
    }
}

// ---------------- conv2 via mma.sync bf16 (hi/lo compensated, 3 passes) ----------------
// CTA: 4 images -> M = 144 positions (rows, A operand), N = 128 oc (B operand), grid (2,128).
// 324 steps = 81 dydx x 4 ci-chunks of 64. Per step stage A[144x64] hi/lo (NHWC strips) and
// B[64ci x 128oc] hi/lo via cp.async, double-buffered. Compute: 4 k16 x 9 m-tiles x 2 n-tiles
// x 3 passes (hh, hl, lh) of mma.m16n8k16. Padded strides (144B, 272B == 16 mod 128) make
// every ldmatrix 8-row group conflict-free.
#define C2_AHI   0u
#define C2_ALO   20736u
#define C2_BHI   41472u
#define C2_BLO   58880u
#define C2_BUFSZ 76288u
#define C2_STEPS 324

__global__ __launch_bounds__(256, 1) void conv2_mma_kernel(const float* __restrict__ bias) {
    extern __shared__ __align__(16) char smc[];
    uint32_t smb = (uint32_t)__cvta_generic_to_shared(smc);
    int t = threadIdx.x;
    int ocbase = blockIdx.x * 128, bq = blockIdx.y;
    int w = t >> 5, T = t & 31;

    // per-thread staging descriptors
    long asrc[5]; uint32_t adst[5]; int an = 0;
#pragma unroll
    for (int i = 0; i < 5; i++) {
        int idx = t + i * 256;
        if (idx < 1152) {
            int row = idx >> 3, c = idx & 7;
            int img = row / 36, p = row - img * 36, oy = p / 6, ox = p - oy * 6;
            asrc[an] = ((long)(bq * 4 + img) * 400 + (long)(2 * oy) * 20 + 2 * ox) * 256 + c * 8;
            adst[an] = (uint32_t)(row * 144 + c * 16);
            an++;
        }
    }
    long bsrc[4]; uint32_t bdst[4];
#pragma unroll
    for (int i = 0; i < 4; i++) {
        int idx = t + i * 256;
        int row = idx >> 4, c = idx & 15;
        bsrc[i] = (long)row * 256 + ocbase + c * 8;
        bdst[i] = (uint32_t)(row * 272 + c * 16);
    }
    const char* hh = (const char*)g_hh;
    const char* hl = (const char*)g_hl;
    const char* wh = (const char*)g_wh;
    const char* wl = (const char*)g_wl;

    // prologue: stage step 0 into buffer 0 (dydx=0, ci0=0)
    {
        uint32_t ba = smb;
        for (int i = 0; i < an; i++) {
            cp16(ba + C2_AHI + adst[i], hh + asrc[i] * 2);
            cp16(ba + C2_ALO + adst[i], hl + asrc[i] * 2);
        }
#pragma unroll
        for (int i = 0; i < 4; i++) {
            cp16(ba + C2_BHI + bdst[i], wh + bsrc[i] * 2);
            cp16(ba + C2_BLO + bdst[i], wl + bsrc[i] * 2);
        }
        cp_commit();
    }

    float acc[9][2][4];
#pragma unroll
    for (int m = 0; m < 9; m++)
#pragma unroll
        for (int n = 0; n < 2; n++)
#pragma unroll
            for (int i = 0; i < 4; i++) acc[m][n][i] = 0.f;

    uint32_t arow = (uint32_t)((T & 15) * 144 + ((T & 16) ? 16 : 0));
    uint32_t brow = (uint32_t)((T & 15) * 272 + w * 32 + ((T & 16) ? 16 : 0));

    for (int s = 0; s < C2_STEPS; s++) {
        // stage step s+1 into other buffer
        if (s + 1 < C2_STEPS) {
            int s1 = s + 1, dydx = s1 >> 2, ci0 = (s1 & 3) * 64;
            int dy = dydx / 9, dx = dydx - dy * 9;
            long stepA = (long)(dy * 20 + dx) * 256 + ci0;
            long stepB = ((long)dydx * 256 + ci0) * 256;
            uint32_t ba = smb + (uint32_t)((s1 & 1) ? C2_BUFSZ : 0u);
            for (int i = 0; i < an; i++) {
                cp16(ba + C2_AHI + adst[i], hh + (asrc[i] + stepA) * 2);
                cp16(ba + C2_ALO + adst[i], hl + (asrc[i] + stepA) * 2);
            }
#pragma unroll
            for (int i = 0; i < 4; i++) {
                cp16(ba + C2_BHI + bdst[i], wh + (bsrc[i] + stepB) * 2);
                cp16(ba + C2_BLO + bdst[i], wl + (bsrc[i] + stepB) * 2);
            }
            cp_commit();
            cp_wait1();      // oldest group (step s) complete
        } else {
            cp_wait0();
        }
        __syncthreads();

        uint32_t base = smb + (uint32_t)((s & 1) ? C2_BUFSZ : 0u);
        uint32_t Ah = base + C2_AHI, Al = base + C2_ALO;
        uint32_t Bh = base + C2_BHI, Bl = base + C2_BLO;
#pragma unroll
        for (int kk = 0; kk < 4; kk++) {
            uint32_t bh[4], bl[4];
            ldsm4t(bh, Bh + (uint32_t)(kk * 16 * 272) + brow);
            ldsm4t(bl, Bl + (uint32_t)(kk * 16 * 272) + brow);
#pragma unroll
            for (int mt = 0; mt < 9; mt++) {
                uint32_t ah[4], al[4];
                uint32_t ao = (uint32_t)(mt * 16 * 144 + kk * 32) + arow;
                ldsm4(ah, Ah + ao);
                ldsm4(al, Al + ao);
                mma16816(acc[mt][0], ah, bh);
                mma16816(acc[mt][1], ah, bh + 2);
                mma16816(acc[mt][0], ah, bl);
                mma16816(acc[mt][1], ah, bl + 2);
                mma16816(acc[mt][0], al, bh);
                mma16816(acc[mt][1], al, bh + 2);
            }
        }
        __syncthreads();
    }

    // epilogue: C[m=pos][n=oc] -> g_u[b][ (oc&31)*36 + p ][ oc>>5 ] + bias
    int gid = T >> 2, tig = T & 3;
#pragma unroll
    for (int nt = 0; nt < 2; nt++) {
        int col = w * 16 + nt * 8 + tig * 2;
        int oc0 = ocbase + col, oc1 = oc0 + 1;
        float bv0 = bias[oc0], bv1 = bias[oc1];
        size_t o0 = (size_t)(oc0 & 31) * 36 * 8 + (oc0 >> 5);
        size_t o1 = (size_t)(oc1 & 31) * 36 * 8 + (oc1 >> 5);
#pragma unroll
        for (int mt = 0; mt < 9; mt++) {
#pragma unroll
            for (int h = 0; h < 2; h++) {
                int row = mt * 16 + gid + h * 8;
                int img = row / 36, p = row - img * 36;
                size_t ubase = ((size_t)(bq * 4 + img) * 1152 + p) * 8;
                g_u[ubase + o0] = acc[mt][nt][h * 2 + 0] + bv0;
                g_u[ubase + o1] = acc[mt][nt][h * 2 + 1] + bv1;
            }
        }
    }
}

// ---------------- squash over capsule dim (8) in place ----------------
__global__ void squash_kernel() {
    int idx = blockIdx.x * 256 + threadIdx.x;
    if (idx >= 512 * 1152) return;
    float4* p = (float4*)(g_u + (size_t)idx * 8);
    float4 a = p[0], b = p[1];
    float sq = a.x*a.x + a.y*a.y + a.z*a.z + a.w*a.w
             + b.x*b.x + b.y*b.y + b.z*b.z + b.w*b.w;
    float sc = sq / ((1.f + sq) * sqrtf(sq));
    a.x *= sc; a.y *= sc; a.z *= sc; a.w *= sc;
    b.x *= sc; b.y *= sc; b.z *= sc; b.w *= sc;
    p[0] = a; p[1] = b;
}

// ---------------- fused priors + dynamic routing: one block per (class, image) ----------------
__global__ __launch_bounds__(256) void routing_kernel(const float* __restrict__ rw) {
    extern __shared__ float smf[];
    float* pr  = smf;                 // 1152*17
    float* lg  = smf + 1152 * 17;     // 1152
    float* red = lg + 1152;           // 8*17
    int c = blockIdx.x, b = blockIdx.y, t = threadIdx.x;
    int lane = t & 31, wid = t >> 5;
    const float* ub  = g_u + (size_t)b * 9216;
    const float* rwc = rw + (size_t)c * 147456;
    for (int r = t; r < 1152; r += 256) {
        const float4* uq = (const float4*)(ub + r * 8);
        float4 u0 = uq[0], u1 = uq[1];
        float uu[8] = {u0.x, u0.y, u0.z, u0.w, u1.x, u1.y, u1.z, u1.w};
        const float4* wp = (const float4*)(rwc + (size_t)r * 128);
        float acc[16];
#pragma unroll
        for (int o = 0; o < 16; o++) acc[o] = 0.f;
#pragma unroll
        for (int i = 0; i < 8; i++) {
            float ui = uu[i];
#pragma unroll
            for (int q = 0; q < 4; q++) {
                float4 wv = wp[i * 4 + q];
                acc[q*4+0] = fmaf(ui, wv.x, acc[q*4+0]);
                acc[q*4+1] = fmaf(ui, wv.y, acc[q*4+1]);
                acc[q*4+2] = fmaf(ui, wv.z, acc[q*4+2]);
                acc[q*4+3] = fmaf(ui, wv.w, acc[q*4+3]);
            }
        }
        float* pp = pr + r * 17;
#pragma unroll
        for (int o = 0; o < 16; o++) pp[o] = acc[o];
        lg[r] = 0.f;
    }
    __syncthreads();
    float v[16];
    for (int it = 0; it < 3; it++) {
        float mx = -3.0e38f;
        for (int r = t; r < 1152; r += 256) mx = fmaxf(mx, lg[r]);
#pragma unroll
        for (int off = 16; off; off >>= 1) mx = fmaxf(mx, __shfl_xor_sync(0xffffffffu, mx, off));
        if (lane == 0) red[wid] = mx;
        __syncthreads();
        float M = fmaxf(fmaxf(fmaxf(red[0], red[1]), fmaxf(red[2], red[3])),
                        fmaxf(fmaxf(red[4], red[5]), fmaxf(red[6], red[7])));
        __syncthreads();
        float s[16];
#pragma unroll
        for (int o = 0; o < 16; o++) s[o] = 0.f;
        float z = 0.f;
        for (int r = t; r < 1152; r += 256) {
            float e = expf(lg[r] - M);
            z += e;
            const float* pp = pr + r * 17;
#pragma unroll
            for (int o = 0; o < 16; o++) s[o] = fmaf(e, pp[o], s[o]);
        }
#pragma unroll
        for (int off = 16; off; off >>= 1) {
            z += __shfl_xor_sync(0xffffffffu, z, off);
#pragma unroll
            for (int o = 0; o < 16; o++) s[o] += __shfl_xor_sync(0xffffffffu, s[o], off);
        }
        if (lane == 0) {
            float* rr = red + wid * 17;
#pragma unroll
            for (int o = 0; o < 16; o++) rr[o] = s[o];
            rr[16] = z;
        }
        __syncthreads();
        float Z = 0.f, S[16];
#pragma unroll
        for (int o = 0; o < 16; o++) S[o] = 0.f;
#pragma unroll
        for (int ww = 0; ww < 8; ww++) {
            const float* rr = red + ww * 17;
            Z += rr[16];
#pragma unroll
            for (int o = 0; o < 16; o++) S[o] += rr[o];
        }
        float sq = 0.f;
#pragma unroll
        for (int o = 0; o < 16; o++) { v[o] = S[o] / Z; sq = fmaf(v[o], v[o], sq); }
        float sc = sq / ((1.f + sq) * sqrtf(sq));
#pragma unroll
        for (int o = 0; o < 16; o++) v[o] *= sc;
        if (it < 2) {
            __syncthreads();
            for (int r = t; r < 1152; r += 256) {
                const float* pp = pr + r * 17;
                float dot = 0.f;
#pragma unroll
                for (int o = 0; o < 16; o++) dot = fmaf(pp[o], v[o], dot);
                lg[r] += dot;
            }
            __syncthreads();
        }
    }
    if (t == 0) {
        float* cp = g_caps + ((size_t)b * NC + c) * 16;
#pragma unroll
        for (int o = 0; o < 16; o++) cp[o] = v[o];
    }
}

// ---------------- classes softmax + argmax mask -> decoder input ----------------
__global__ void classes_kernel(float* __restrict__ out_classes) {
    int b = blockIdx.x, lane = threadIdx.x;  // 32 threads
    float n2 = 0.f;
    if (lane < NC) {
        const float* cp = g_caps + ((size_t)b * NC + lane) * 16;
#pragma unroll
        for (int o = 0; o < 16; o++) n2 = fmaf(cp[o], cp[o], n2);
    }
    float nrm = (lane < NC) ? sqrtf(n2) : -3.0e38f;
    float mx = nrm;
#pragma unroll
    for (int off = 16; off; off >>= 1) mx = fmaxf(mx, __shfl_xor_sync(0xffffffffu, mx, off));
    float e = (lane < NC) ? expf(nrm - mx) : 0.f;
    float zz = e;
#pragma unroll
    for (int off = 16; off; off >>= 1) zz += __shfl_xor_sync(0xffffffffu, zz, off);
    if (lane < NC) out_classes[b * NC + lane] = e / zz;
    unsigned msk = __ballot_sync(0xffffffffu, nrm == mx);
    int am = __ffs(msk) - 1;
    const float* ap = g_caps + ((size_t)b * NC + am) * 16;
    for (int j = lane; j < 160; j += 32)
        g_d0[b * 160 + j] = ((j >> 4) == am) ? ap[j & 15] : 0.f;
}

// ---------------- decoder GEMM: C[512,N] = act(A[512,K] @ W[N,K]^T + bias) ----------------
__global__ __launch_bounds__(256) void gemm_kernel(const float* __restrict__ A,
                                                   const float* __restrict__ W,
                                                   const float* __restrict__ bias,
                                                   float* __restrict__ C,
                                                   int N, int K, int act) {
    __shared__ float As[64][33];
    __shared__ float Bs[64][33];
    int tx = threadIdx.x & 15, ty = threadIdx.x >> 4;
    int m0 = blockIdx.y * 64, n0 = blockIdx.x * 64;
    float acc[4][4];
#pragma unroll
    for (int i = 0; i < 4; i++)
#pragma unroll
        for (int j = 0; j < 4; j++) acc[i][j] = 0.f;
    for (int k0 = 0; k0 < K; k0 += 32) {
        __syncthreads();
        for (int idx = threadIdx.x; idx < 2048; idx += 256) {
            int mm = idx >> 5, kk = idx & 31;
            As[mm][kk] = A[(size_t)(m0 + mm) * K + k0 + kk];
            Bs[mm][kk] = (n0 + mm < N) ? W[(size_t)(n0 + mm) * K + k0 + kk] : 0.f;
        }
        __syncthreads();
#pragma unroll
        for (int kk = 0; kk < 32; kk++) {
            float a[4], bb[4];
#pragma unroll
            for (int i = 0; i < 4; i++) a[i] = As[ty * 4 + i][kk];
#pragma unroll
            for (int j = 0; j < 4; j++) bb[j] = Bs[tx * 4 + j][kk];
#pragma unroll
            for (int i = 0; i < 4; i++)
#pragma unroll
                for (int j = 0; j < 4; j++) acc[i][j] = fmaf(a[i], bb[j], acc[i][j]);
        }
    }
#pragma unroll
    for (int i = 0; i < 4; i++) {
        int cm = m0 + ty * 4 + i;
#pragma unroll
        for (int j = 0; j < 4; j++) {
            int cn = n0 + tx * 4 + j;
            if (cn < N) {
                float val = acc[i][j] + bias[cn];
                val = act ? (1.f / (1.f + expf(-val))) : fmaxf(val, 0.f);
                C[(size_t)cm * N + cn] = val;
            }
        }
    }
}

extern "C" void kernel_launch(void* const* d_in, const int* in_sizes, int n_in,
                              void* d_out, int out_size) {
    const float* x   = (const float*)d_in[0];
    const float* c1w = (const float*)d_in[1];
    const float* c1b = (const float*)d_in[2];
    const float* pw  = (const float*)d_in[3];
    const float* pb  = (const float*)d_in[4];
    const float* rw  = (const float*)d_in[5];
    const float* w1  = (const float*)d_in[6];
    const float* b1  = (const float*)d_in[7];
    const float* w2  = (const float*)d_in[8];
    const float* b2  = (const float*)d_in[9];
    const float* w3  = (const float*)d_in[10];
    const float* b3  = (const float*)d_in[11];
    float* out = (float*)d_out;
    float* out_classes = out;              // [512,10]
    float* out_recon   = out + 512 * NC;   // [512,784]

    void *p_d0, *p_d1, *p_d2;
    cudaGetSymbolAddress(&p_d0, g_d0);
    cudaGetSymbolAddress(&p_d1, g_d1);
    cudaGetSymbolAddress(&p_d2, g_d2);

    prep_w_kernel<<<256, 256>>>(pw);
    conv1_kernel<<<dim3(8, 512), 640>>>(x, c1w, c1b);

    int c2sm = 2 * C2_BUFSZ;  // 152576 B
    cudaFuncSetAttribute(conv2_mma_kernel, cudaFuncAttributeMaxDynamicSharedMemorySize, c2sm);
    conv2_mma_kernel<<<dim3(2, 128), 256, c2sm>>>(pb);

    squash_kernel<<<(512 * 1152 + 255) / 256, 256>>>();

    size_t rsm = (size_t)(1152 * 17 + 1152 + 136) * sizeof(float);  // 83488 B
    cudaFuncSetAttribute(routing_kernel, cudaFuncAttributeMaxDynamicSharedMemorySize, (int)rsm);
    routing_kernel<<<dim3(10, 512), 256, rsm>>>(rw);

    classes_kernel<<<512, 32>>>(out_classes);

    gemm_kernel<<<dim3(8, 8),  256>>>((const float*)p_d0, w1, b1, (float*)p_d1, 512, 160, 0);
    gemm_kernel<<<dim3(16, 8), 256>>>((const float*)p_d1, w2, b2, (float*)p_d2, 1024, 512, 0);
    gemm_kernel<<<dim3(13, 8), 256>>>((const float*)p_d2, w3, b3, out_recon, 784, 1024, 1);
}

// round 6
// speedup vs baseline: 2.0022x; 1.0443x over previous
#include <cuda_runtime.h>
#include <cuda_bf16.h>
#include <math.h>
#include <stdint.h>

#define NC 10

// ---------------- scratch (static device arrays; no runtime allocation) ----------------
__device__ __nv_bfloat16 g_hh[52428800];  // [512 b][20 y][20 x][256 c] conv1 out, bf16 hi
__device__ __nv_bfloat16 g_hl[52428800];  // same, bf16 lo (residual)
__device__ __nv_bfloat16 g_wh[5308416];   // [81 dydx][256 ci][256 oc] weights hi
__device__ __nv_bfloat16 g_wl[5308416];   // weights lo
__device__ float g_u[4718592];            // [512][1152][8] primary capsules
__device__ float g_caps[81920];           // [512][10][16]
__device__ float g_d0[81920];             // [512][160]
__device__ float g_d1[262144];            // [512][512]
__device__ float g_d2[524288];            // [512][1024]

// ---------------- PTX helpers (all baseline sm_80+; no arch-'a' features) ----------------
__device__ __forceinline__ void cp16(uint32_t d, const void* s) {
    asm volatile("cp.async.cg.shared.global [%0], [%1], 16;" :: "r"(d), "l"(s));
}
__device__ __forceinline__ void cp_commit() { asm volatile("cp.async.commit_group;"); }
__device__ __forceinline__ void cp_wait0()  { asm volatile("cp.async.wait_group 0;" ::: "memory"); }
__device__ __forceinline__ void cp_wait1()  { asm volatile("cp.async.wait_group 1;" ::: "memory"); }

__device__ __forceinline__ void ldsm4(uint32_t* r, uint32_t addr) {
    asm volatile("ldmatrix.sync.aligned.m8n8.x4.shared.b16 {%0,%1,%2,%3}, [%4];"
        : "=r"(r[0]), "=r"(r[1]), "=r"(r[2]), "=r"(r[3]) : "r"(addr));
}
__device__ __forceinline__ void ldsm4t(uint32_t* r, uint32_t addr) {
    asm volatile("ldmatrix.sync.aligned.m8n8.x4.trans.shared.b16 {%0,%1,%2,%3}, [%4];"
        : "=r"(r[0]), "=r"(r[1]), "=r"(r[2]), "=r"(r[3]) : "r"(addr));
}
__device__ __forceinline__ void mma16816(float* c, const uint32_t* a, const uint32_t* b) {
    asm volatile("mma.sync.aligned.m16n8k16.row.col.f32.bf16.bf16.f32 "
        "{%0,%1,%2,%3}, {%4,%5,%6,%7}, {%8,%9}, {%0,%1,%2,%3};"
        : "+f"(c[0]), "+f"(c[1]), "+f"(c[2]), "+f"(c[3])
        : "r"(a[0]), "r"(a[1]), "r"(a[2]), "r"(a[3]), "r"(b[0]), "r"(b[1]));
}

// ---------------- weight prep: prim_w [256 oc][256 ci][81] -> [dydx][ci][oc] hi/lo bf16 ----------
__global__ void prep_w_kernel(const float* __restrict__ pw) {
    int idx = blockIdx.x * 256 + threadIdx.x;   // 65536 = ci*256 + oc
    int ci = idx >> 8, oc = idx & 255;
    const float* src = pw + (size_t)(oc * 256 + ci) * 81;
#pragma unroll 3
    for (int k = 0; k < 81; k++) {
        float w = src[k];
        __nv_bfloat16 hi = __float2bfloat16(w);
        __nv_bfloat16 lo = __float2bfloat16(w - __bfloat162float(hi));
        size_t o = ((size_t)k * 256 + ci) * 256 + oc;
        g_wh[o] = hi;
        g_wl[o] = lo;
    }
}

// ---------------- conv1: x[512,1,28,28] * w[256,1,9,9] -> relu -> NHWC bf16 hi/lo ----------------
__global__ __launch_bounds__(640) void conv1_kernel(const float* __restrict__ x,
                                                    const float* __restrict__ w,
                                                    const float* __restrict__ bias) {
    __shared__ __align__(16) float img[784];
    __shared__ float ws[2592];
    __shared__ float bs[32];
    int b = blockIdx.y, ocg = blockIdx.x, t = threadIdx.x;
    const float4* xim = (const float4*)(x + (size_t)b * 784);
    for (int i = t; i < 196; i += 640) ((float4*)img)[i] = xim[i];
    for (int i = t; i < 2592; i += 640) ws[i] = w[(size_t)ocg * 2592 + i];
    if (t < 32) bs[t] = bias[ocg * 32 + t];
    __syncthreads();
    int oc = t & 31, y = t >> 5;
    float acc[20];
#pragma unroll
    for (int i = 0; i < 20; i++) acc[i] = 0.f;
    for (int dy = 0; dy < 9; dy++) {
        float row[28];
        const float4* rp = (const float4*)&img[(y + dy) * 28];
#pragma unroll
        for (int i = 0; i < 7; i++) {
            float4 v = rp[i];
            row[4*i] = v.x; row[4*i+1] = v.y; row[4*i+2] = v.z; row[4*i+3] = v.w;
        }
#pragma unroll
        for (int dx = 0; dx < 9; dx++) {
            float wv = ws[oc * 81 + dy * 9 + dx];
#pragma unroll
            for (int xo = 0; xo < 20; xo++) acc[xo] = fmaf(wv, row[xo + dx], acc[xo]);
        }
    }
    float bv = bs[oc];
    size_t base = (((size_t)b * 20 + y) * 20) * 256 + ocg * 32 + oc;
#pragma unroll
    for (int i = 0; i < 20; i++) {
        float val = fmaxf(acc[i] + bv, 0.f);
        __nv_bfloat16 hi = __float2bfloat16(val);
        __nv_bfloat16 lo = __float2bfloat16(val - __bfloat162float(hi));
        g_hh[base + (size_t)i * 256] = hi;
        g_hl[base + (size_t)i * 256] = lo;
    }
}

// ---------------- conv2 via mma.sync bf16 (hi/lo compensated, 3 passes) ----------------
// CTA: 4 images -> M=144 positions, N=256 oc (all), 512 threads / 16 warps, grid 128 (0.86 wave).
// 324 steps = 81 dydx x 4 ci-chunks of 64. A[144x64] hi/lo + B[64ci x 256oc] hi/lo staged via
// cp.async, double-buffered. Each warp owns an N=16 slice. Padded strides (144B, 528B == 16
// mod 128) keep ldmatrix conflict-free.
#define C2_AHI   0u
#define C2_ALO   20736u
#define C2_BHI   41472u
#define C2_BLO   75264u
#define C2_BUFSZ 109056u
#define C2_STEPS 324

__global__ __launch_bounds__(512, 1) void conv2_mma_kernel(const float* __restrict__ bias) {
    extern __shared__ __align__(16) char smc[];
    uint32_t smb = (uint32_t)__cvta_generic_to_shared(smc);
    int t = threadIdx.x;
    int bq = blockIdx.x;
    int w = t >> 5, T = t & 31;

    // per-thread staging descriptors (byte offsets, fit in uint32)
    uint32_t asrc[3], adst[3]; int an = 0;
#pragma unroll
    for (int i = 0; i < 3; i++) {
        int idx = t + i * 512;
        if (idx < 1152) {
            int row = idx >> 3, c = idx & 7;
            int img = row / 36, p = row - img * 36, oy = p / 6, ox = p - oy * 6;
            asrc[an] = (uint32_t)((((long)(bq * 4 + img) * 400 + (long)(2 * oy) * 20 + 2 * ox) * 256 + c * 8) * 2);
            adst[an] = (uint32_t)(row * 144 + c * 16);
            an++;
        }
    }
    uint32_t bsrc[4], bdst[4];
#pragma unroll
    for (int i = 0; i < 4; i++) {
        int idx = t + i * 512;          // 2048 chunks: 64 rows x 32 chunks
        int row = idx >> 5, c = idx & 31;
        bsrc[i] = (uint32_t)((row * 256 + c * 8) * 2);
        bdst[i] = (uint32_t)(row * 528 + c * 16);
    }
    const char* hh = (const char*)g_hh;
    const char* hl = (const char*)g_hl;
    const char* wh = (const char*)g_wh;
    const char* wl = (const char*)g_wl;

    // prologue: stage step 0 into buffer 0 (dydx=0, ci0=0)
    {
        uint32_t ba = smb;
        for (int i = 0; i < an; i++) {
            cp16(ba + C2_AHI + adst[i], hh + asrc[i]);
            cp16(ba + C2_ALO + adst[i], hl + asrc[i]);
        }
#pragma unroll
        for (int i = 0; i < 4; i++) {
            cp16(ba + C2_BHI + bdst[i], wh + bsrc[i]);
            cp16(ba + C2_BLO + bdst[i], wl + bsrc[i]);
        }
        cp_commit();
    }

    float acc[9][2][4];
#pragma unroll
    for (int m = 0; m < 9; m++)
#pragma unroll
        for (int n = 0; n < 2; n++)
#pragma unroll
            for (int i = 0; i < 4; i++) acc[m][n][i] = 0.f;

    uint32_t arow = (uint32_t)((T & 15) * 144 + ((T & 16) ? 16 : 0));
    uint32_t brow = (uint32_t)((T & 15) * 528 + w * 32 + ((T & 16) ? 16 : 0));

    for (int s = 0; s < C2_STEPS; s++) {
        // stage step s+1 into other buffer
        if (s + 1 < C2_STEPS) {
            int s1 = s + 1, dydx = s1 >> 2, ci0 = (s1 & 3) * 64;
            int dy = dydx / 9, dx = dydx - dy * 9;
            uint32_t stepA = (uint32_t)(((dy * 20 + dx) * 256 + ci0) * 2);
            uint32_t stepB = (uint32_t)(((dydx * 256 + ci0) * 256) * 2);
            uint32_t ba = smb + (uint32_t)((s1 & 1) ? C2_BUFSZ : 0u);
            for (int i = 0; i < an; i++) {
                cp16(ba + C2_AHI + adst[i], hh + asrc[i] + stepA);
                cp16(ba + C2_ALO + adst[i], hl + asrc[i] + stepA);
            }
#pragma unroll
            for (int i = 0; i < 4; i++) {
                cp16(ba + C2_BHI + bdst[i], wh + bsrc[i] + stepB);
                cp16(ba + C2_BLO + bdst[i], wl + bsrc[i] + stepB);
            }
            cp_commit();
            cp_wait1();      // oldest group (step s) complete
        } else {
            cp_wait0();
        }
        __syncthreads();

        uint32_t base = smb + (uint32_t)((s & 1) ? C2_BUFSZ : 0u);
        uint32_t Ah = base + C2_AHI, Al = base + C2_ALO;
        uint32_t Bh = base + C2_BHI, Bl = base + C2_BLO;
#pragma unroll
        for (int kk = 0; kk < 4; kk++) {
            uint32_t bh[4], bl[4];
            ldsm4t(bh, Bh + (uint32_t)(kk * 16 * 528) + brow);
            ldsm4t(bl, Bl + (uint32_t)(kk * 16 * 528) + brow);
#pragma unroll
            for (int mt = 0; mt < 9; mt++) {
                uint32_t ah[4], al[4];
                uint32_t ao = (uint32_t)(mt * 16 * 144 + kk * 32) + arow;
                ldsm4(ah, Ah + ao);
                ldsm4(al, Al + ao);
                mma16816(acc[mt][0], ah, bh);
                mma16816(acc[mt][1], ah, bh + 2);
                mma16816(acc[mt][0], ah, bl);
                mma16816(acc[mt][1], ah, bl + 2);
                mma16816(acc[mt][0], al, bh);
                mma16816(acc[mt][1], al, bh + 2);
            }
        }
        __syncthreads();
    }

    // epilogue: C[m=pos][n=oc] -> g_u[b][ (oc&31)*36 + p ][ oc>>5 ] + bias
    int gid = T >> 2, tig = T & 3;
#pragma unroll
    for (int nt = 0; nt < 2; nt++) {
        int oc0 = w * 16 + nt * 8 + tig * 2;
        int oc1 = oc0 + 1;
        float bv0 = bias[oc0], bv1 = bias[oc1];
        size_t o0 = (size_t)(oc0 & 31) * 36 * 8 + (oc0 >> 5);
        size_t o1 = (size_t)(oc1 & 31) * 36 * 8 + (oc1 >> 5);
#pragma unroll
        for (int mt = 0; mt < 9; mt++) {
#pragma unroll
            for (int h = 0; h < 2; h++) {
                int row = mt * 16 + gid + h * 8;
                int img = row / 36, p = row - img * 36;
                size_t ubase = ((size_t)(bq * 4 + img) * 1152 + p) * 8;
                g_u[ubase + o0] = acc[mt][nt][h * 2 + 0] + bv0;
                g_u[ubase + o1] = acc[mt][nt][h * 2 + 1] + bv1;
            }
        }
    }
}

// ---------------- squash over capsule dim (8) in place ----------------
__global__ void squash_kernel() {
    int idx = blockIdx.x * 256 + threadIdx.x;
    if (idx >= 512 * 1152) return;
    float4* p = (float4*)(g_u + (size_t)idx * 8);
    float4 a = p[0], b = p[1];
    float sq = a.x*a.x + a.y*a.y + a.z*a.z + a.w*a.w
             + b.x*b.x + b.y*b.y + b.z*b.z + b.w*b.w;
    float sc = sq / ((1.f + sq) * sqrtf(sq));
    a.x *= sc; a.y *= sc; a.z *= sc; a.w *= sc;
    b.x *= sc; b.y *= sc; b.z *= sc; b.w *= sc;
    p[0] = a; p[1] = b;
}

// ---------------- fused priors + dynamic routing, register-resident ----------------
// One block per (class, image), 384 threads x 3 routes. Priors+logits live in registers;
// iterations are pure shuffle + 17-value cross-warp smem reductions. route_w read once.
__global__ __launch_bounds__(384) void routing_kernel(const float* __restrict__ rw) {
    __shared__ float red[12 * 17];
    __shared__ float mred[12];
    int c = blockIdx.x, b = blockIdx.y, t = threadIdx.x;
    int lane = t & 31, wid = t >> 5;
    const float* ub  = g_u + (size_t)b * 9216;
    const float* rwc = rw + (size_t)c * 147456;

    float pr[3][16];
    float lg[3] = {0.f, 0.f, 0.f};
#pragma unroll
    for (int i = 0; i < 3; i++) {
        int r = t + i * 384;
        const float4* uq = (const float4*)(ub + r * 8);
        float4 u0 = uq[0], u1 = uq[1];
        float uu[8] = {u0.x, u0.y, u0.z, u0.w, u1.x, u1.y, u1.z, u1.w};
        const float4* wp = (const float4*)(rwc + (size_t)r * 128);
#pragma unroll
        for (int o = 0; o < 16; o++) pr[i][o] = 0.f;
#pragma unroll
        for (int k = 0; k < 8; k++) {
            float ui = uu[k];
#pragma unroll
            for (int q = 0; q < 4; q++) {
                float4 wv = wp[k * 4 + q];
                pr[i][q*4+0] = fmaf(ui, wv.x, pr[i][q*4+0]);
                pr[i][q*4+1] = fmaf(ui, wv.y, pr[i][q*4+1]);
                pr[i][q*4+2] = fmaf(ui, wv.z, pr[i][q*4+2]);
                pr[i][q*4+3] = fmaf(ui, wv.w, pr[i][q*4+3]);
            }
        }
    }

    float v[16];
    for (int it = 0; it < 3; it++) {
        // block max of logits
        float mx = fmaxf(fmaxf(lg[0], lg[1]), lg[2]);
#pragma unroll
        for (int off = 16; off; off >>= 1) mx = fmaxf(mx, __shfl_xor_sync(0xffffffffu, mx, off));
        if (lane == 0) mred[wid] = mx;
        __syncthreads();
        float M = mred[0];
#pragma unroll
        for (int ww = 1; ww < 12; ww++) M = fmaxf(M, mred[ww]);

        // weighted sums
        float s[16];
#pragma unroll
        for (int o = 0; o < 16; o++) s[o] = 0.f;
        float z = 0.f;
#pragma unroll
        for (int i = 0; i < 3; i++) {
            float e = expf(lg[i] - M);
            z += e;
#pragma unroll
            for (int o = 0; o < 16; o++) s[o] = fmaf(e, pr[i][o], s[o]);
        }
#pragma unroll
        for (int off = 16; off; off >>= 1) {
            z += __shfl_xor_sync(0xffffffffu, z, off);
#pragma unroll
            for (int o = 0; o < 16; o++) s[o] += __shfl_xor_sync(0xffffffffu, s[o], off);
        }
        if (lane == 0) {
            float* rr = red + wid * 17;
#pragma unroll
            for (int o = 0; o < 16; o++) rr[o] = s[o];
            rr[16] = z;
        }
        __syncthreads();
        float Z = 0.f, S[16];
#pragma unroll
        for (int o = 0; o < 16; o++) S[o] = 0.f;
#pragma unroll
        for (int ww = 0; ww < 12; ww++) {
            const float* rr = red + ww * 17;
            Z += rr[16];
#pragma unroll
            for (int o = 0; o < 16; o++) S[o] += rr[o];
        }
        float sq = 0.f;
#pragma unroll
        for (int o = 0; o < 16; o++) { v[o] = S[o] / Z; sq = fmaf(v[o], v[o], sq); }
        float sc = sq / ((1.f + sq) * sqrtf(sq));
#pragma unroll
        for (int o = 0; o < 16; o++) v[o] *= sc;
        if (it < 2) {
#pragma unroll
            for (int i = 0; i < 3; i++) {
                float dot = 0.f;
#pragma unroll
                for (int o = 0; o < 16; o++) dot = fmaf(pr[i][o], v[o], dot);
                lg[i] += dot;
            }
        }
        __syncthreads();   // protect red/mred before next iteration's writes
    }
    if (t == 0) {
        float* cp = g_caps + ((size_t)b * NC + c) * 16;
#pragma unroll
        for (int o = 0; o < 16; o++) cp[o] = v[o];
    }
}

// ---------------- classes softmax + argmax mask -> decoder input ----------------
__global__ void classes_kernel(float* __restrict__ out_classes) {
    int b = blockIdx.x, lane = threadIdx.x;  // 32 threads
    float n2 = 0.f;
    if (lane < NC) {
        const float* cp = g_caps + ((size_t)b * NC + lane) * 16;
#pragma unroll
        for (int o = 0; o < 16; o++) n2 = fmaf(cp[o], cp[o], n2);
    }
    float nrm = (lane < NC) ? sqrtf(n2) : -3.0e38f;
    float mx = nrm;
#pragma unroll
    for (int off = 16; off; off >>= 1) mx = fmaxf(mx, __shfl_xor_sync(0xffffffffu, mx, off));
    float e = (lane < NC) ? expf(nrm - mx) : 0.f;
    float zz = e;
#pragma unroll
    for (int off = 16; off; off >>= 1) zz += __shfl_xor_sync(0xffffffffu, zz, off);
    if (lane < NC) out_classes[b * NC + lane] = e / zz;
    unsigned msk = __ballot_sync(0xffffffffu, nrm == mx);
    int am = __ffs(msk) - 1;
    const float* ap = g_caps + ((size_t)b * NC + am) * 16;
    for (int j = lane; j < 160; j += 32)
        g_d0[b * 160 + j] = ((j >> 4) == am) ? ap[j & 15] : 0.f;
}

// ---------------- decoder GEMM: C[512,N] = act(A[512,K] @ W[N,K]^T + bias) ----------------
__global__ __launch_bounds__(256) void gemm_kernel(const float* __restrict__ A,
                                                   const float* __restrict__ W,
                                                   const float* __restrict__ bias,
                                                   float* __restrict__ C,
                                                   int N, int K, int act) {
    __shared__ float As[64][33];
    __shared__ float Bs[64][33];
    int tx = threadIdx.x & 15, ty = threadIdx.x >> 4;
    int m0 = blockIdx.y * 64, n0 = blockIdx.x * 64;
    float acc[4][4];
#pragma unroll
    for (int i = 0; i < 4; i++)
#pragma unroll
        for (int j = 0; j < 4; j++) acc[i][j] = 0.f;
    for (int k0 = 0; k0 < K; k0 += 32) {
        __syncthreads();
        for (int idx = threadIdx.x; idx < 2048; idx += 256) {
            int mm = idx >> 5, kk = idx & 31;
            As[mm][kk] = A[(size_t)(m0 + mm) * K + k0 + kk];
            Bs[mm][kk] = (n0 + mm < N) ? W[(size_t)(n0 + mm) * K + k0 + kk] : 0.f;
        }
        __syncthreads();
#pragma unroll
        for (int kk = 0; kk < 32; kk++) {
            float a[4], bb[4];
#pragma unroll
            for (int i = 0; i < 4; i++) a[i] = As[ty * 4 + i][kk];
#pragma unroll
            for (int j = 0; j < 4; j++) bb[j] = Bs[tx * 4 + j][kk];
#pragma unroll
            for (int i = 0; i < 4; i++)
#pragma unroll
                for (int j = 0; j < 4; j++) acc[i][j] = fmaf(a[i], bb[j], acc[i][j]);
        }
    }
#pragma unroll
    for (int i = 0; i < 4; i++) {
        int cm = m0 + ty * 4 + i;
#pragma unroll
        for (int j = 0; j < 4; j++) {
            int cn = n0 + tx * 4 + j;
            if (cn < N) {
                float val = acc[i][j] + bias[cn];
                val = act ? (1.f / (1.f + expf(-val))) : fmaxf(val, 0.f);
                C[(size_t)cm * N + cn] = val;
            }
        }
    }
}

extern "C" void kernel_launch(void* const* d_in, const int* in_sizes, int n_in,
                              void* d_out, int out_size) {
    const float* x   = (const float*)d_in[0];
    const float* c1w = (const float*)d_in[1];
    const float* c1b = (const float*)d_in[2];
    const float* pw  = (const float*)d_in[3];
    const float* pb  = (const float*)d_in[4];
    const float* rw  = (const float*)d_in[5];
    const float* w1  = (const float*)d_in[6];
    const float* b1  = (const float*)d_in[7];
    const float* w2  = (const float*)d_in[8];
    const float* b2  = (const float*)d_in[9];
    const float* w3  = (const float*)d_in[10];
    const float* b3  = (const float*)d_in[11];
    float* out = (float*)d_out;
    float* out_classes = out;              // [512,10]
    float* out_recon   = out + 512 * NC;   // [512,784]

    void *p_d0, *p_d1, *p_d2;
    cudaGetSymbolAddress(&p_d0, g_d0);
    cudaGetSymbolAddress(&p_d1, g_d1);
    cudaGetSymbolAddress(&p_d2, g_d2);

    prep_w_kernel<<<256, 256>>>(pw);
    conv1_kernel<<<dim3(8, 512), 640>>>(x, c1w, c1b);

    int c2sm = 2 * C2_BUFSZ;  // 218112 B
    cudaFuncSetAttribute(conv2_mma_kernel, cudaFuncAttributeMaxDynamicSharedMemorySize, c2sm);
    conv2_mma_kernel<<<128, 512, c2sm>>>(pb);

    squash_kernel<<<(512 * 1152 + 255) / 256, 256>>>();

    routing_kernel<<<dim3(10, 512), 384>>>(rw);

    classes_kernel<<<512, 32>>>(out_classes);

    gemm_kernel<<<dim3(8, 8),  256>>>((const float*)p_d0, w1, b1, (float*)p_d1, 512, 160, 0);
    gemm_kernel<<<dim3(16, 8), 256>>>((const float*)p_d1, w2, b2, (float*)p_d2, 1024, 512, 0);
    gemm_kernel<<<dim3(13, 8), 256>>>((const float*)p_d2, w3, b3, out_recon, 784, 1024, 1);
}

// round 7
// speedup vs baseline: 2.2760x; 1.1368x over previous
#include <cuda_runtime.h>
#include <cuda_bf16.h>
#include <math.h>
#include <stdint.h>

#define NC 10

// ---------------- scratch (static device arrays; no runtime allocation) ----------------
__device__ __nv_bfloat16 g_hh[52428800];  // [512 b][20 y][20 x][256 c] conv1 out, bf16 hi
__device__ __nv_bfloat16 g_hl[52428800];  // same, bf16 lo (residual)
__device__ __nv_bfloat16 g_wh[5308416];   // [81 dydx][256 ci][256 oc] weights hi
__device__ __nv_bfloat16 g_wl[5308416];   // weights lo
__device__ float g_rw2[1474560];          // [10 c][128 io][1152 r] transposed route_w
__device__ float g_u[4718592];            // [512][1152][8] primary capsules
__device__ float g_caps[81920];           // [512][10][16]
__device__ float g_d0[81920];             // [512][160]
__device__ float g_d1[262144];            // [512][512]
__device__ float g_d2[524288];            // [512][1024]

// ---------------- PTX helpers (all baseline sm_80+; no arch-'a' features) ----------------
__device__ __forceinline__ void cp16(uint32_t d, const void* s) {
    asm volatile("cp.async.cg.shared.global [%0], [%1], 16;" :: "r"(d), "l"(s));
}
__device__ __forceinline__ void cp_commit() { asm volatile("cp.async.commit_group;"); }
__device__ __forceinline__ void cp_wait0()  { asm volatile("cp.async.wait_group 0;" ::: "memory"); }
__device__ __forceinline__ void cp_wait1()  { asm volatile("cp.async.wait_group 1;" ::: "memory"); }

__device__ __forceinline__ void ldsm4(uint32_t* r, uint32_t addr) {
    asm volatile("ldmatrix.sync.aligned.m8n8.x4.shared.b16 {%0,%1,%2,%3}, [%4];"
        : "=r"(r[0]), "=r"(r[1]), "=r"(r[2]), "=r"(r[3]) : "r"(addr));
}
__device__ __forceinline__ void ldsm4t(uint32_t* r, uint32_t addr) {
    asm volatile("ldmatrix.sync.aligned.m8n8.x4.trans.shared.b16 {%0,%1,%2,%3}, [%4];"
        : "=r"(r[0]), "=r"(r[1]), "=r"(r[2]), "=r"(r[3]) : "r"(addr));
}
__device__ __forceinline__ void mma16816(float* c, const uint32_t* a, const uint32_t* b) {
    asm volatile("mma.sync.aligned.m16n8k16.row.col.f32.bf16.bf16.f32 "
        "{%0,%1,%2,%3}, {%4,%5,%6,%7}, {%8,%9}, {%0,%1,%2,%3};"
        : "+f"(c[0]), "+f"(c[1]), "+f"(c[2]), "+f"(c[3])
        : "r"(a[0]), "r"(a[1]), "r"(a[2]), "r"(a[3]), "r"(b[0]), "r"(b[1]));
}

// ---------------- weight prep: prim_w [256 oc][256 ci][81] -> [dydx][ci][oc] hi/lo bf16 ----------
__global__ void prep_w_kernel(const float* __restrict__ pw) {
    int idx = blockIdx.x * 256 + threadIdx.x;   // 65536 = ci*256 + oc
    int ci = idx >> 8, oc = idx & 255;
    const float* src = pw + (size_t)(oc * 256 + ci) * 81;
#pragma unroll 3
    for (int k = 0; k < 81; k++) {
        float w = src[k];
        __nv_bfloat16 hi = __float2bfloat16(w);
        __nv_bfloat16 lo = __float2bfloat16(w - __bfloat162float(hi));
        size_t o = ((size_t)k * 256 + ci) * 256 + oc;
        g_wh[o] = hi;
        g_wl[o] = lo;
    }
}

// ---------------- route_w transpose: [c][r][i][o] -> [c][io][r] (coalesced both sides) --------
__global__ __launch_bounds__(256) void prep_rw_kernel(const float* __restrict__ rw) {
    __shared__ float tile[32][33];
    int rb = blockIdx.x, iob = blockIdx.y, c = blockIdx.z;
    int tx = threadIdx.x & 31, ty = threadIdx.x >> 5;   // ty 0..7
#pragma unroll
    for (int k = 0; k < 4; k++) {
        int r = rb * 32 + ty * 4 + k;
        tile[ty * 4 + k][tx] = rw[((size_t)c * 1152 + r) * 128 + iob * 32 + tx];
    }
    __syncthreads();
#pragma unroll
    for (int k = 0; k < 4; k++) {
        int io = iob * 32 + ty * 4 + k;
        g_rw2[((size_t)c * 128 + io) * 1152 + rb * 32 + tx] = tile[tx][ty * 4 + k];
    }
}

// ---------------- conv1: x[512,1,28,28] * w[256,1,9,9] -> relu -> NHWC bf16 hi/lo ----------------
__global__ __launch_bounds__(640) void conv1_kernel(const float* __restrict__ x,
                                                    const float* __restrict__ w,
                                                    const float* __restrict__ bias) {
    __shared__ __align__(16) float img[784];
    __shared__ float ws[2592];
    __shared__ float bs[32];
    int b = blockIdx.y, ocg = blockIdx.x, t = threadIdx.x;
    const float4* xim = (const float4*)(x + (size_t)b * 784);
    for (int i = t; i < 196; i += 640) ((float4*)img)[i] = xim[i];
    for (int i = t; i < 2592; i += 640) ws[i] = w[(size_t)ocg * 2592 + i];
    if (t < 32) bs[t] = bias[ocg * 32 + t];
    __syncthreads();
    int oc = t & 31, y = t >> 5;
    float acc[20];
#pragma unroll
    for (int i = 0; i < 20; i++) acc[i] = 0.f;
    for (int dy = 0; dy < 9; dy++) {
        float row[28];
        const float4* rp = (const float4*)&img[(y + dy) * 28];
#pragma unroll
        for (int i = 0; i < 7; i++) {
            float4 v = rp[i];
            row[4*i] = v.x; row[4*i+1] = v.y; row[4*i+2] = v.z; row[4*i+3] = v.w;
        }
#pragma unroll
        for (int dx = 0; dx < 9; dx++) {
            float wv = ws[oc * 81 + dy * 9 + dx];
#pragma unroll
            for (int xo = 0; xo < 20; xo++) acc[xo] = fmaf(wv, row[xo + dx], acc[xo]);
        }
    }
    float bv = bs[oc];
    size_t base = (((size_t)b * 20 + y) * 20) * 256 + ocg * 32 + oc;
#pragma unroll
    for (int i = 0; i < 20; i++) {
        float val = fmaxf(acc[i] + bv, 0.f);
        __nv_bfloat16 hi = __float2bfloat16(val);
        __nv_bfloat16 lo = __float2bfloat16(val - __bfloat162float(hi));
        g_hh[base + (size_t)i * 256] = hi;
        g_hl[base + (size_t)i * 256] = lo;
    }
}

// ---------------- conv2 via mma.sync bf16 (hi/lo compensated, 3 passes) ----------------
// CTA: 4 images -> M=144 positions, N=256 oc (all), 512 threads / 16 warps, grid 128 (0.86 wave).
#define C2_AHI   0u
#define C2_ALO   20736u
#define C2_BHI   41472u
#define C2_BLO   75264u
#define C2_BUFSZ 109056u
#define C2_STEPS 324

__global__ __launch_bounds__(512, 1) void conv2_mma_kernel(const float* __restrict__ bias) {
    extern __shared__ __align__(16) char smc[];
    uint32_t smb = (uint32_t)__cvta_generic_to_shared(smc);
    int t = threadIdx.x;
    int bq = blockIdx.x;
    int w = t >> 5, T = t & 31;

    // per-thread staging descriptors (byte offsets, fit in uint32)
    uint32_t asrc[3], adst[3]; int an = 0;
#pragma unroll
    for (int i = 0; i < 3; i++) {
        int idx = t + i * 512;
        if (idx < 1152) {
            int row = idx >> 3, c = idx & 7;
            int img = row / 36, p = row - img * 36, oy = p / 6, ox = p - oy * 6;
            asrc[an] = (uint32_t)((((long)(bq * 4 + img) * 400 + (long)(2 * oy) * 20 + 2 * ox) * 256 + c * 8) * 2);
            adst[an] = (uint32_t)(row * 144 + c * 16);
            an++;
        }
    }
    uint32_t bsrc[4], bdst[4];
#pragma unroll
    for (int i = 0; i < 4; i++) {
        int idx = t + i * 512;          // 2048 chunks: 64 rows x 32 chunks
        int row = idx >> 5, c = idx & 31;
        bsrc[i] = (uint32_t)((row * 256 + c * 8) * 2);
        bdst[i] = (uint32_t)(row * 528 + c * 16);
    }
    const char* hh = (const char*)g_hh;
    const char* hl = (const char*)g_hl;
    const char* wh = (const char*)g_wh;
    const char* wl = (const char*)g_wl;

    // prologue: stage step 0 into buffer 0 (dydx=0, ci0=0)
    {
        uint32_t ba = smb;
        for (int i = 0; i < an; i++) {
            cp16(ba + C2_AHI + adst[i], hh + asrc[i]);
            cp16(ba + C2_ALO + adst[i], hl + asrc[i]);
        }
#pragma unroll
        for (int i = 0; i < 4; i++) {
            cp16(ba + C2_BHI + bdst[i], wh + bsrc[i]);
            cp16(ba + C2_BLO + bdst[i], wl + bsrc[i]);
        }
        cp_commit();
    }

    float acc[9][2][4];
#pragma unroll
    for (int m = 0; m < 9; m++)
#pragma unroll
        for (int n = 0; n < 2; n++)
#pragma unroll
            for (int i = 0; i < 4; i++) acc[m][n][i] = 0.f;

    uint32_t arow = (uint32_t)((T & 15) * 144 + ((T & 16) ? 16 : 0));
    uint32_t brow = (uint32_t)((T & 15) * 528 + w * 32 + ((T & 16) ? 16 : 0));

    for (int s = 0; s < C2_STEPS; s++) {
        if (s + 1 < C2_STEPS) {
            int s1 = s + 1, dydx = s1 >> 2, ci0 = (s1 & 3) * 64;
            int dy = dydx / 9, dx = dydx - dy * 9;
            uint32_t stepA = (uint32_t)(((dy * 20 + dx) * 256 + ci0) * 2);
            uint32_t stepB = (uint32_t)(((dydx * 256 + ci0) * 256) * 2);
            uint32_t ba = smb + (uint32_t)((s1 & 1) ? C2_BUFSZ : 0u);
            for (int i = 0; i < an; i++) {
                cp16(ba + C2_AHI + adst[i], hh + asrc[i] + stepA);
                cp16(ba + C2_ALO + adst[i], hl + asrc[i] + stepA);
            }
#pragma unroll
            for (int i = 0; i < 4; i++) {
                cp16(ba + C2_BHI + bdst[i], wh + bsrc[i] + stepB);
                cp16(ba + C2_BLO + bdst[i], wl + bsrc[i] + stepB);
            }
            cp_commit();
            cp_wait1();
        } else {
            cp_wait0();
        }
        __syncthreads();

        uint32_t base = smb + (uint32_t)((s & 1) ? C2_BUFSZ : 0u);
        uint32_t Ah = base + C2_AHI, Al = base + C2_ALO;
        uint32_t Bh = base + C2_BHI, Bl = base + C2_BLO;
#pragma unroll
        for (int kk = 0; kk < 4; kk++) {
            uint32_t bh[4], bl[4];
            ldsm4t(bh, Bh + (uint32_t)(kk * 16 * 528) + brow);
            ldsm4t(bl, Bl + (uint32_t)(kk * 16 * 528) + brow);
#pragma unroll
            for (int mt = 0; mt < 9; mt++) {
                uint32_t ah[4], al[4];
                uint32_t ao = (uint32_t)(mt * 16 * 144 + kk * 32) + arow;
                ldsm4(ah, Ah + ao);
                ldsm4(al, Al + ao);
                mma16816(acc[mt][0], ah, bh);
                mma16816(acc[mt][1], ah, bh + 2);
                mma16816(acc[mt][0], ah, bl);
                mma16816(acc[mt][1], ah, bl + 2);
                mma16816(acc[mt][0], al, bh);
                mma16816(acc[mt][1], al, bh + 2);
            }
        }
        __syncthreads();
    }

    // epilogue: C[m=pos][n=oc] -> g_u[b][ (oc&31)*36 + p ][ oc>>5 ] + bias
    int gid = T >> 2, tig = T & 3;
#pragma unroll
    for (int nt = 0; nt < 2; nt++) {
        int oc0 = w * 16 + nt * 8 + tig * 2;
        int oc1 = oc0 + 1;
        float bv0 = bias[oc0], bv1 = bias[oc1];
        size_t o0 = (size_t)(oc0 & 31) * 36 * 8 + (oc0 >> 5);
        size_t o1 = (size_t)(oc1 & 31) * 36 * 8 + (oc1 >> 5);
#pragma unroll
        for (int mt = 0; mt < 9; mt++) {
#pragma unroll
            for (int h = 0; h < 2; h++) {
                int row = mt * 16 + gid + h * 8;
                int img = row / 36, p = row - img * 36;
                size_t ubase = ((size_t)(bq * 4 + img) * 1152 + p) * 8;
                g_u[ubase + o0] = acc[mt][nt][h * 2 + 0] + bv0;
                g_u[ubase + o1] = acc[mt][nt][h * 2 + 1] + bv1;
            }
        }
    }
}

// ---------------- squash over capsule dim (8) in place ----------------
__global__ void squash_kernel() {
    int idx = blockIdx.x * 256 + threadIdx.x;
    if (idx >= 512 * 1152) return;
    float4* p = (float4*)(g_u + (size_t)idx * 8);
    float4 a = p[0], b = p[1];
    float sq = a.x*a.x + a.y*a.y + a.z*a.z + a.w*a.w
             + b.x*b.x + b.y*b.y + b.z*b.z + b.w*b.w;
    float sc = sq / ((1.f + sq) * sqrtf(sq));
    a.x *= sc; a.y *= sc; a.z *= sc; a.w *= sc;
    b.x *= sc; b.y *= sc; b.z *= sc; b.w *= sc;
    p[0] = a; p[1] = b;
}

// ---------------- routing: block = (class, 2 images), 576 threads x 2 routes ----------------
// Priors in registers; route_w read from transposed g_rw2 (lane-consecutive, coalesced) and
// shared by both images -> half the L2 traffic, 1 wavefront per load instead of 32.
__global__ __launch_bounds__(576) void routing_kernel() {
    __shared__ float red[18][2][17];
    __shared__ float mred[18][2];
    int c = blockIdx.x, b0 = blockIdx.y * 2, t = threadIdx.x;
    int lane = t & 31, wid = t >> 5;
    const float* w  = g_rw2 + (size_t)c * 147456;
    const float* u0 = g_u + (size_t)b0 * 9216;
    const float* u1 = g_u + (size_t)(b0 + 1) * 9216;

    float pr[2][2][16];
#pragma unroll
    for (int a = 0; a < 2; a++)
#pragma unroll
        for (int j = 0; j < 2; j++)
#pragma unroll
            for (int o = 0; o < 16; o++) pr[a][j][o] = 0.f;

#pragma unroll
    for (int i = 0; i < 8; i++) {
        float a00 = u0[t * 8 + i],          a01 = u0[(t + 576) * 8 + i];
        float a10 = u1[t * 8 + i],          a11 = u1[(t + 576) * 8 + i];
#pragma unroll
        for (int o = 0; o < 16; o++) {
            const float* wp = w + (size_t)(i * 16 + o) * 1152;
            float w0 = wp[t], w1 = wp[t + 576];
            pr[0][0][o] = fmaf(a00, w0, pr[0][0][o]);
            pr[0][1][o] = fmaf(a01, w1, pr[0][1][o]);
            pr[1][0][o] = fmaf(a10, w0, pr[1][0][o]);
            pr[1][1][o] = fmaf(a11, w1, pr[1][1][o]);
        }
    }

    float lg[2][2] = {{0.f, 0.f}, {0.f, 0.f}};
    float s0[16], s1[16];
    for (int it = 0; it < 3; it++) {
        // block max of logits (per image)
        float mx0 = fmaxf(lg[0][0], lg[0][1]);
        float mx1 = fmaxf(lg[1][0], lg[1][1]);
#pragma unroll
        for (int off = 16; off; off >>= 1) {
            mx0 = fmaxf(mx0, __shfl_xor_sync(0xffffffffu, mx0, off));
            mx1 = fmaxf(mx1, __shfl_xor_sync(0xffffffffu, mx1, off));
        }
        if (lane == 0) { mred[wid][0] = mx0; mred[wid][1] = mx1; }
        __syncthreads();
        float M0 = mred[0][0], M1 = mred[0][1];
#pragma unroll
        for (int ww = 1; ww < 18; ww++) {
            M0 = fmaxf(M0, mred[ww][0]);
            M1 = fmaxf(M1, mred[ww][1]);
        }

        // weighted sums
#pragma unroll
        for (int o = 0; o < 16; o++) { s0[o] = 0.f; s1[o] = 0.f; }
        float z0 = 0.f, z1 = 0.f;
#pragma unroll
        for (int j = 0; j < 2; j++) {
            float e0 = expf(lg[0][j] - M0);
            float e1 = expf(lg[1][j] - M1);
            z0 += e0; z1 += e1;
#pragma unroll
            for (int o = 0; o < 16; o++) {
                s0[o] = fmaf(e0, pr[0][j][o], s0[o]);
                s1[o] = fmaf(e1, pr[1][j][o], s1[o]);
            }
        }
#pragma unroll
        for (int off = 16; off; off >>= 1) {
            z0 += __shfl_xor_sync(0xffffffffu, z0, off);
            z1 += __shfl_xor_sync(0xffffffffu, z1, off);
#pragma unroll
            for (int o = 0; o < 16; o++) {
                s0[o] += __shfl_xor_sync(0xffffffffu, s0[o], off);
                s1[o] += __shfl_xor_sync(0xffffffffu, s1[o], off);
            }
        }
        if (lane == 0) {
#pragma unroll
            for (int o = 0; o < 16; o++) { red[wid][0][o] = s0[o]; red[wid][1][o] = s1[o]; }
            red[wid][0][16] = z0; red[wid][1][16] = z1;
        }
        __syncthreads();
        float Z0 = 0.f, Z1 = 0.f;
#pragma unroll
        for (int o = 0; o < 16; o++) { s0[o] = 0.f; s1[o] = 0.f; }
#pragma unroll
        for (int ww = 0; ww < 18; ww++) {
            Z0 += red[ww][0][16]; Z1 += red[ww][1][16];
#pragma unroll
            for (int o = 0; o < 16; o++) {
                s0[o] += red[ww][0][o];
                s1[o] += red[ww][1][o];
            }
        }
        // squash -> v (in place in s)
        float q0 = 0.f, q1 = 0.f;
#pragma unroll
        for (int o = 0; o < 16; o++) {
            s0[o] /= Z0; q0 = fmaf(s0[o], s0[o], q0);
            s1[o] /= Z1; q1 = fmaf(s1[o], s1[o], q1);
        }
        float c0 = q0 / ((1.f + q0) * sqrtf(q0));
        float c1 = q1 / ((1.f + q1) * sqrtf(q1));
#pragma unroll
        for (int o = 0; o < 16; o++) { s0[o] *= c0; s1[o] *= c1; }
        if (it < 2) {
#pragma unroll
            for (int j = 0; j < 2; j++) {
                float d0 = 0.f, d1 = 0.f;
#pragma unroll
                for (int o = 0; o < 16; o++) {
                    d0 = fmaf(pr[0][j][o], s0[o], d0);
                    d1 = fmaf(pr[1][j][o], s1[o], d1);
                }
                lg[0][j] += d0; lg[1][j] += d1;
            }
        }
        __syncthreads();   // protect red/mred before next iteration's writes
    }
    if (t == 0) {
        float* cp0 = g_caps + ((size_t)b0 * NC + c) * 16;
        float* cp1 = g_caps + ((size_t)(b0 + 1) * NC + c) * 16;
#pragma unroll
        for (int o = 0; o < 16; o++) { cp0[o] = s0[o]; cp1[o] = s1[o]; }
    }
}

// ---------------- classes softmax + argmax mask -> decoder input ----------------
__global__ void classes_kernel(float* __restrict__ out_classes) {
    int b = blockIdx.x, lane = threadIdx.x;  // 32 threads
    float n2 = 0.f;
    if (lane < NC) {
        const float* cp = g_caps + ((size_t)b * NC + lane) * 16;
#pragma unroll
        for (int o = 0; o < 16; o++) n2 = fmaf(cp[o], cp[o], n2);
    }
    float nrm = (lane < NC) ? sqrtf(n2) : -3.0e38f;
    float mx = nrm;
#pragma unroll
    for (int off = 16; off; off >>= 1) mx = fmaxf(mx, __shfl_xor_sync(0xffffffffu, mx, off));
    float e = (lane < NC) ? expf(nrm - mx) : 0.f;
    float zz = e;
#pragma unroll
    for (int off = 16; off; off >>= 1) zz += __shfl_xor_sync(0xffffffffu, zz, off);
    if (lane < NC) out_classes[b * NC + lane] = e / zz;
    unsigned msk = __ballot_sync(0xffffffffu, nrm == mx);
    int am = __ffs(msk) - 1;
    const float* ap = g_caps + ((size_t)b * NC + am) * 16;
    for (int j = lane; j < 160; j += 32)
        g_d0[b * 160 + j] = ((j >> 4) == am) ? ap[j & 15] : 0.f;
}

// ---------------- decoder GEMM: C[512,N] = act(A[512,K] @ W[N,K]^T + bias) ----------------
__global__ __launch_bounds__(256) void gemm_kernel(const float* __restrict__ A,
                                                   const float* __restrict__ W,
                                                   const float* __restrict__ bias,
                                                   float* __restrict__ C,
                                                   int N, int K, int act) {
    __shared__ float As[64][33];
    __shared__ float Bs[64][33];
    int tx = threadIdx.x & 15, ty = threadIdx.x >> 4;
    int m0 = blockIdx.y * 64, n0 = blockIdx.x * 64;
    float acc[4][4];
#pragma unroll
    for (int i = 0; i < 4; i++)
#pragma unroll
        for (int j = 0; j < 4; j++) acc[i][j] = 0.f;
    for (int k0 = 0; k0 < K; k0 += 32) {
        __syncthreads();
        for (int idx = threadIdx.x; idx < 2048; idx += 256) {
            int mm = idx >> 5, kk = idx & 31;
            As[mm][kk] = A[(size_t)(m0 + mm) * K + k0 + kk];
            Bs[mm][kk] = (n0 + mm < N) ? W[(size_t)(n0 + mm) * K + k0 + kk] : 0.f;
        }
        __syncthreads();
#pragma unroll
        for (int kk = 0; kk < 32; kk++) {
            float a[4], bb[4];
#pragma unroll
            for (int i = 0; i < 4; i++) a[i] = As[ty * 4 + i][kk];
#pragma unroll
            for (int j = 0; j < 4; j++) bb[j] = Bs[tx * 4 + j][kk];
#pragma unroll
            for (int i = 0; i < 4; i++)
#pragma unroll
                for (int j = 0; j < 4; j++) acc[i][j] = fmaf(a[i], bb[j], acc[i][j]);
        }
    }
#pragma unroll
    for (int i = 0; i < 4; i++) {
        int cm = m0 + ty * 4 + i;
#pragma unroll
        for (int j = 0; j < 4; j++) {
            int cn = n0 + tx * 4 + j;
            if (cn < N) {
                float val = acc[i][j] + bias[cn];
                val = act ? (1.f / (1.f + expf(-val))) : fmaxf(val, 0.f);
                C[(size_t)cm * N + cn] = val;
            }
        }
    }
}

extern "C" void kernel_launch(void* const* d_in, const int* in_sizes, int n_in,
                              void* d_out, int out_size) {
    const float* x   = (const float*)d_in[0];
    const float* c1w = (const float*)d_in[1];
    const float* c1b = (const float*)d_in[2];
    const float* pw  = (const float*)d_in[3];
    const float* pb  = (const float*)d_in[4];
    const float* rw  = (const float*)d_in[5];
    const float* w1  = (const float*)d_in[6];
    const float* b1  = (const float*)d_in[7];
    const float* w2  = (const float*)d_in[8];
    const float* b2  = (const float*)d_in[9];
    const float* w3  = (const float*)d_in[10];
    const float* b3  = (const float*)d_in[11];
    float* out = (float*)d_out;
    float* out_classes = out;              // [512,10]
    float* out_recon   = out + 512 * NC;   // [512,784]

    void *p_d0, *p_d1, *p_d2;
    cudaGetSymbolAddress(&p_d0, g_d0);
    cudaGetSymbolAddress(&p_d1, g_d1);
    cudaGetSymbolAddress(&p_d2, g_d2);

    prep_w_kernel<<<256, 256>>>(pw);                    // launch 1
    prep_rw_kernel<<<dim3(36, 4, 10), 256>>>(rw);       // launch 2
    conv1_kernel<<<dim3(8, 512), 640>>>(x, c1w, c1b);   // launch 3

    int c2sm = 2 * C2_BUFSZ;  // 218112 B
    cudaFuncSetAttribute(conv2_mma_kernel, cudaFuncAttributeMaxDynamicSharedMemorySize, c2sm);
    conv2_mma_kernel<<<128, 512, c2sm>>>(pb);           // launch 4 (profiled slot)

    squash_kernel<<<(512 * 1152 + 255) / 256, 256>>>();

    routing_kernel<<<dim3(10, 256), 576>>>();

    classes_kernel<<<512, 32>>>(out_classes);

    gemm_kernel<<<dim3(8, 8),  256>>>((const float*)p_d0, w1, b1, (float*)p_d1, 512, 160, 0);
    gemm_kernel<<<dim3(16, 8), 256>>>((const float*)p_d1, w2, b2, (float*)p_d2, 1024, 512, 0);
    gemm_kernel<<<dim3(13, 8), 256>>>((const float*)p_d2, w3, b3, out_recon, 784, 1024, 1);
}